// round 3
// baseline (speedup 1.0000x reference)
#include <cuda_runtime.h>
#include <cstddef>

#define BB 8
#define CC 256
#define NN 4096            // tokens = 64*64
#define GG 32              // groups
#define CPG 8              // channels per group

// ---------------- scratch (device globals: allocation-free) ----------------
__device__ float g_h[(size_t)BB * CC * NN];          // normalized input  (33.5 MB)
__device__ float g_qkv[(size_t)BB * 3 * CC * NN];    // q,k,v             (100 MB)
__device__ float g_att[(size_t)BB * CC * NN];        // attention output  (33.5 MB)

// ============================ GroupNorm =====================================
// grid (32 groups, 8 batches), 256 threads. Each group = 8 contiguous channels
// x 4096 spatial = 32768 contiguous floats.
__global__ void __launch_bounds__(256) gn_kernel(const float* __restrict__ x,
                                                 const float* __restrict__ w,
                                                 const float* __restrict__ bg,
                                                 float* __restrict__ h)
{
    const int g = blockIdx.x, b = blockIdx.y;
    const size_t base = ((size_t)b * CC + (size_t)g * CPG) * NN;
    const float* xp = x + base;
    float* hp = h + base;
    const int tid = threadIdx.x;

    float s = 0.f, ss = 0.f;
#pragma unroll
    for (int t = 0; t < 32; t++) {
        float4 v = *reinterpret_cast<const float4*>(xp + (size_t)(t * 256 + tid) * 4);
        s  += v.x + v.y + v.z + v.w;
        ss += v.x * v.x + v.y * v.y + v.z * v.z + v.w * v.w;
    }
#pragma unroll
    for (int o = 16; o; o >>= 1) {
        s  += __shfl_xor_sync(0xffffffffu, s, o);
        ss += __shfl_xor_sync(0xffffffffu, ss, o);
    }
    __shared__ float rs[8], rss[8], stats[2];
    if ((tid & 31) == 0) { rs[tid >> 5] = s; rss[tid >> 5] = ss; }
    __syncthreads();
    if (tid == 0) {
        float ts = 0.f, tss = 0.f;
#pragma unroll
        for (int i = 0; i < 8; i++) { ts += rs[i]; tss += rss[i]; }
        const float inv_n = 1.0f / (CPG * NN);
        float mu = ts * inv_n;
        float var = tss * inv_n - mu * mu;
        stats[0] = mu;
        stats[1] = rsqrtf(var + 1e-5f);
    }
    __syncthreads();
    const float mu = stats[0], rsg = stats[1];
#pragma unroll
    for (int t = 0; t < 32; t++) {
        const int idx = (t * 256 + tid) * 4;
        const int c = g * CPG + (idx >> 12);      // idx/4096
        const float sc = w[c] * rsg;
        const float sh = bg[c] - mu * sc;
        float4 v = *reinterpret_cast<const float4*>(xp + idx);
        v.x = v.x * sc + sh; v.y = v.y * sc + sh;
        v.z = v.z * sc + sh; v.w = v.w * sc + sh;
        *reinterpret_cast<float4*>(hp + idx) = v;
    }
}

// ============================ tiled SGEMM ===================================
// out[b][o][n] = sum_c W[o][c] * X[b][c][n] + bias[o] (+ resid[b][o][n])
// K = 256, N = 4096 fixed; M passed (768 for qkv, 256 for proj).
// Block tile 64(M) x 64(N), K-step 16, 256 threads, 4x4 microtile.
__global__ void __launch_bounds__(256) gemm_kernel(const float* __restrict__ W,
                                                   const float* __restrict__ X,
                                                   const float* __restrict__ bias,
                                                   const float* __restrict__ resid,
                                                   float* __restrict__ out,
                                                   int M)
{
    const int K = 256, N = NN;
    __shared__ float sW[16 * 65];   // [k][o], stride 65 (conflict-free)
    __shared__ float sX[16 * 64];   // [k][n]

    const int tid = threadIdx.x;
    const int tx = tid & 15, ty = tid >> 4;
    const int n0 = blockIdx.x * 64, m0 = blockIdx.y * 64, b = blockIdx.z;
    const float* Xb = X + (size_t)b * K * N;

    float4 acc[4];
#pragma unroll
    for (int i = 0; i < 4; i++) acc[i] = make_float4(0.f, 0.f, 0.f, 0.f);

    for (int k0 = 0; k0 < K; k0 += 16) {
#pragma unroll
        for (int t = 0; t < 4; t++) {
            int idx = tid + t * 256;          // 0..1023
            int o = idx >> 4, k = idx & 15;
            sW[k * 65 + o] = W[(size_t)(m0 + o) * K + k0 + k];
        }
#pragma unroll
        for (int t = 0; t < 4; t++) {
            int idx = tid + t * 256;
            int k = idx >> 6, n = idx & 63;
            sX[k * 64 + n] = Xb[(size_t)(k0 + k) * N + n0 + n];
        }
        __syncthreads();
#pragma unroll
        for (int kk = 0; kk < 16; kk++) {
            float4 xv = *reinterpret_cast<float4*>(sX + kk * 64 + tx * 4);
            float a0 = sW[kk * 65 + ty * 4 + 0];
            float a1 = sW[kk * 65 + ty * 4 + 1];
            float a2 = sW[kk * 65 + ty * 4 + 2];
            float a3 = sW[kk * 65 + ty * 4 + 3];
            acc[0].x += a0 * xv.x; acc[0].y += a0 * xv.y; acc[0].z += a0 * xv.z; acc[0].w += a0 * xv.w;
            acc[1].x += a1 * xv.x; acc[1].y += a1 * xv.y; acc[1].z += a1 * xv.z; acc[1].w += a1 * xv.w;
            acc[2].x += a2 * xv.x; acc[2].y += a2 * xv.y; acc[2].z += a2 * xv.z; acc[2].w += a2 * xv.w;
            acc[3].x += a3 * xv.x; acc[3].y += a3 * xv.y; acc[3].z += a3 * xv.z; acc[3].w += a3 * xv.w;
        }
        __syncthreads();
    }
#pragma unroll
    for (int i = 0; i < 4; i++) {
        const int o = m0 + ty * 4 + i;
        const float bv = bias[o];
        float4 r = acc[i];
        r.x += bv; r.y += bv; r.z += bv; r.w += bv;
        const size_t off = ((size_t)b * M + o) * N + n0 + tx * 4;
        if (resid) {
            float4 rv = *reinterpret_cast<const float4*>(resid + off);
            r.x += rv.x; r.y += rv.y; r.z += rv.z; r.w += rv.w;
        }
        *reinterpret_cast<float4*>(out + off) = r;
    }
}

// ========================= flash attention (fp32) ===========================
// S[q][k] = (1/16) * sum_c Q[c][q] K[c][k];  P = online-softmax(S) over k;
// O[c][q] = sum_k P[q][k] V[c][k].
// Block: 64 queries, full c=256. Streams 64-wide K/V tiles (V reuses K buffer).
// SMEM floats: sQ 256*64, sKV 256*64, sS 64*65, sP 64*68, m/l/alpha 3*64.
#define SQ_OFF  0
#define SKV_OFF 16384
#define SS_OFF  32768
#define SP_OFF  (SS_OFF + 64 * 65)
#define SM_OFF  (SP_OFF + 64 * 68)
#define SL_OFF  (SM_OFF + 64)
#define SA_OFF  (SL_OFF + 64)
#define ATT_SMEM_FLOATS (SA_OFF + 64)
#define ATT_SMEM_BYTES (ATT_SMEM_FLOATS * 4)

__global__ void __launch_bounds__(256) attn_kernel(const float* __restrict__ qkv,
                                                   float* __restrict__ outp)
{
    extern __shared__ float smf[];
    float* sQ  = smf + SQ_OFF;    // [c][64]
    float* sKV = smf + SKV_OFF;   // [c][64]
    float* sS  = smf + SS_OFF;    // [q][65]
    float* sP  = smf + SP_OFF;    // [k][68]
    float* sMv = smf + SM_OFF;
    float* sLv = smf + SL_OFF;
    float* sAl = smf + SA_OFF;

    const int tid = threadIdx.x;
    const int b = blockIdx.y;
    const int q0 = blockIdx.x * 64;

    const float* Qg = qkv + (size_t)b * 3 * CC * NN;
    const float* Kg = Qg + (size_t)CC * NN;
    const float* Vg = Kg + (size_t)CC * NN;

    // load Q tile: sQ[c*64 + q]
#pragma unroll
    for (int t = 0; t < 16; t++) {
        int idx = tid + t * 256;            // float4 units, 0..4095
        int c = idx >> 4;
        int q4 = (idx & 15) << 2;
        *reinterpret_cast<float4*>(sQ + c * 64 + q4) =
            *reinterpret_cast<const float4*>(Qg + (size_t)c * NN + q0 + q4);
    }
    if (tid < 64) { sMv[tid] = -1e30f; sLv[tid] = 0.f; }

    float4 o_acc[16];
#pragma unroll
    for (int i = 0; i < 16; i++) o_acc[i] = make_float4(0.f, 0.f, 0.f, 0.f);

    const int tx = tid & 15, ty = tid >> 4;
    const int qi = tx * 4, ki = ty * 4;     // S-phase mapping
    const int qo = tx * 4, cb = ty * 16;    // O-phase mapping

    for (int kt = 0; kt < 64; kt++) {
        const int k0 = kt * 64;
        __syncthreads();                    // prev V reads done; sQ/m/l visible (iter 0)
        // load K tile
#pragma unroll
        for (int t = 0; t < 16; t++) {
            int idx = tid + t * 256;
            int c = idx >> 4;
            int k4 = (idx & 15) << 2;
            *reinterpret_cast<float4*>(sKV + c * 64 + k4) =
                *reinterpret_cast<const float4*>(Kg + (size_t)c * NN + k0 + k4);
        }
        __syncthreads();

        // S = Q^T K  (4q x 4k per thread)
        float4 accv[4];
#pragma unroll
        for (int j = 0; j < 4; j++) accv[j] = make_float4(0.f, 0.f, 0.f, 0.f);
#pragma unroll 8
        for (int c = 0; c < CC; c++) {
            float4 qv = *reinterpret_cast<float4*>(sQ + c * 64 + qi);
            float4 kv = *reinterpret_cast<float4*>(sKV + c * 64 + ki);
            accv[0].x += qv.x * kv.x; accv[0].y += qv.y * kv.x; accv[0].z += qv.z * kv.x; accv[0].w += qv.w * kv.x;
            accv[1].x += qv.x * kv.y; accv[1].y += qv.y * kv.y; accv[1].z += qv.z * kv.y; accv[1].w += qv.w * kv.y;
            accv[2].x += qv.x * kv.z; accv[2].y += qv.y * kv.z; accv[2].z += qv.z * kv.z; accv[2].w += qv.w * kv.z;
            accv[3].x += qv.x * kv.w; accv[3].y += qv.y * kv.w; accv[3].z += qv.z * kv.w; accv[3].w += qv.w * kv.w;
        }
        const float scale = 0.0625f;        // 256^-0.5
#pragma unroll
        for (int j = 0; j < 4; j++) {
            sS[(qi + 0) * 65 + ki + j] = accv[j].x * scale;
            sS[(qi + 1) * 65 + ki + j] = accv[j].y * scale;
            sS[(qi + 2) * 65 + ki + j] = accv[j].z * scale;
            sS[(qi + 3) * 65 + ki + j] = accv[j].w * scale;
        }
        __syncthreads();                    // sS complete; K reads complete

        // load V tile (overwrites K buffer)
#pragma unroll
        for (int t = 0; t < 16; t++) {
            int idx = tid + t * 256;
            int c = idx >> 4;
            int k4 = (idx & 15) << 2;
            *reinterpret_cast<float4*>(sKV + c * 64 + k4) =
                *reinterpret_cast<const float4*>(Vg + (size_t)c * NN + k0 + k4);
        }
        // online softmax: one thread per query row
        if (tid < 64) {
            const int q = tid;
            float mo = sMv[q];
            float mx = mo;
#pragma unroll 8
            for (int k = 0; k < 64; k++) mx = fmaxf(mx, sS[q * 65 + k]);
            float al = __expf(mo - mx);
            float l = sLv[q] * al;
#pragma unroll 8
            for (int k = 0; k < 64; k++) {
                float p = __expf(sS[q * 65 + k] - mx);
                sP[k * 68 + q] = p;         // transposed store
                l += p;
            }
            sMv[q] = mx; sLv[q] = l; sAl[q] = al;
        }
        __syncthreads();                    // V + sP + alpha visible

        // rescale O, then O += V * P
        float4 a4 = *reinterpret_cast<float4*>(sAl + qo);
#pragma unroll
        for (int i = 0; i < 16; i++) {
            o_acc[i].x *= a4.x; o_acc[i].y *= a4.y; o_acc[i].z *= a4.z; o_acc[i].w *= a4.w;
        }
#pragma unroll 4
        for (int k = 0; k < 64; k++) {
            float4 p = *reinterpret_cast<float4*>(sP + k * 68 + qo);
#pragma unroll
            for (int i = 0; i < 16; i++) {
                float v = sKV[(cb + i) * 64 + k];
                o_acc[i].x = fmaf(v, p.x, o_acc[i].x);
                o_acc[i].y = fmaf(v, p.y, o_acc[i].y);
                o_acc[i].z = fmaf(v, p.z, o_acc[i].z);
                o_acc[i].w = fmaf(v, p.w, o_acc[i].w);
            }
        }
    }

    // epilogue: O /= l
    float4 l4 = *reinterpret_cast<float4*>(sLv + qo);
    float4 inv = make_float4(1.f / l4.x, 1.f / l4.y, 1.f / l4.z, 1.f / l4.w);
#pragma unroll
    for (int i = 0; i < 16; i++) {
        float4 r;
        r.x = o_acc[i].x * inv.x; r.y = o_acc[i].y * inv.y;
        r.z = o_acc[i].z * inv.z; r.w = o_acc[i].w * inv.w;
        *reinterpret_cast<float4*>(outp + ((size_t)b * CC + cb + i) * NN + q0 + qo) = r;
    }
}

// ================================ launch ====================================
extern "C" void kernel_launch(void* const* d_in, const int* in_sizes, int n_in,
                              void* d_out, int out_size)
{
    const float* x     = (const float*)d_in[0];
    const float* nw    = (const float*)d_in[1];
    const float* nb    = (const float*)d_in[2];
    const float* qkvw  = (const float*)d_in[3];
    const float* qkvb  = (const float*)d_in[4];
    const float* projw = (const float*)d_in[5];
    const float* projb = (const float*)d_in[6];
    float* out = (float*)d_out;

    float *hbuf, *qkvbuf, *abuf;
    cudaGetSymbolAddress((void**)&hbuf, g_h);
    cudaGetSymbolAddress((void**)&qkvbuf, g_qkv);
    cudaGetSymbolAddress((void**)&abuf, g_att);

    cudaFuncSetAttribute(attn_kernel, cudaFuncAttributeMaxDynamicSharedMemorySize,
                         ATT_SMEM_BYTES);

    gn_kernel<<<dim3(GG, BB), 256>>>(x, nw, nb, hbuf);
    gemm_kernel<<<dim3(NN / 64, (3 * CC) / 64, BB), 256>>>(qkvw, hbuf, qkvb, nullptr,
                                                           qkvbuf, 3 * CC);
    attn_kernel<<<dim3(NN / 64, BB), 256, ATT_SMEM_BYTES>>>(qkvbuf, abuf);
    gemm_kernel<<<dim3(NN / 64, CC / 64, BB), 256>>>(projw, abuf, projb, x, out, CC);
}

// round 4
// speedup vs baseline: 2.2542x; 2.2542x over previous
#include <cuda_runtime.h>
#include <cstddef>
#include <cstdint>

#define BB 8
#define CC 256
#define NN 4096            // tokens = 64*64
#define GG 32              // groups
#define CPG 8              // channels per group

// ---------------- scratch (device globals: allocation-free) ----------------
__device__ float g_h[(size_t)BB * CC * NN];          // normalized input
__device__ float g_qkv[(size_t)BB * 3 * CC * NN];    // q,k,v
__device__ float g_att[(size_t)BB * CC * NN];        // attention output

// ============================ helpers =======================================
__device__ __forceinline__ float tf32r(float x) {
    float r;
    asm("cvt.rna.tf32.f32 %0, %1;" : "=f"(r) : "f"(x));
    return r;
}

__device__ __forceinline__ void mma_tf32(float4& d,
                                         uint32_t a0, uint32_t a1, uint32_t a2, uint32_t a3,
                                         uint32_t b0, uint32_t b1) {
    asm volatile(
        "mma.sync.aligned.m16n8k8.row.col.f32.tf32.tf32.f32 "
        "{%0,%1,%2,%3}, {%4,%5,%6,%7}, {%8,%9}, {%0,%1,%2,%3};"
        : "+f"(d.x), "+f"(d.y), "+f"(d.z), "+f"(d.w)
        : "r"(a0), "r"(a1), "r"(a2), "r"(a3), "r"(b0), "r"(b1));
}

// ============================ GroupNorm =====================================
__global__ void __launch_bounds__(256) gn_kernel(const float* __restrict__ x,
                                                 const float* __restrict__ w,
                                                 const float* __restrict__ bg,
                                                 float* __restrict__ h)
{
    const int g = blockIdx.x, b = blockIdx.y;
    const size_t base = ((size_t)b * CC + (size_t)g * CPG) * NN;
    const float* xp = x + base;
    float* hp = h + base;
    const int tid = threadIdx.x;

    float s = 0.f, ss = 0.f;
#pragma unroll
    for (int t = 0; t < 32; t++) {
        float4 v = *reinterpret_cast<const float4*>(xp + (size_t)(t * 256 + tid) * 4);
        s  += v.x + v.y + v.z + v.w;
        ss += v.x * v.x + v.y * v.y + v.z * v.z + v.w * v.w;
    }
#pragma unroll
    for (int o = 16; o; o >>= 1) {
        s  += __shfl_xor_sync(0xffffffffu, s, o);
        ss += __shfl_xor_sync(0xffffffffu, ss, o);
    }
    __shared__ float rs[8], rss[8], stats[2];
    if ((tid & 31) == 0) { rs[tid >> 5] = s; rss[tid >> 5] = ss; }
    __syncthreads();
    if (tid == 0) {
        float ts = 0.f, tss = 0.f;
#pragma unroll
        for (int i = 0; i < 8; i++) { ts += rs[i]; tss += rss[i]; }
        const float inv_n = 1.0f / (CPG * NN);
        float mu = ts * inv_n;
        float var = tss * inv_n - mu * mu;
        stats[0] = mu;
        stats[1] = rsqrtf(var + 1e-5f);
    }
    __syncthreads();
    const float mu = stats[0], rsg = stats[1];
#pragma unroll
    for (int t = 0; t < 32; t++) {
        const int idx = (t * 256 + tid) * 4;
        const int c = g * CPG + (idx >> 12);
        const float sc = w[c] * rsg;
        const float sh = bg[c] - mu * sc;
        float4 v = *reinterpret_cast<const float4*>(xp + idx);
        v.x = v.x * sc + sh; v.y = v.y * sc + sh;
        v.z = v.z * sc + sh; v.w = v.w * sc + sh;
        *reinterpret_cast<float4*>(hp + idx) = v;
    }
}

// ============================ tiled SGEMM ===================================
__global__ void __launch_bounds__(256) gemm_kernel(const float* __restrict__ W,
                                                   const float* __restrict__ X,
                                                   const float* __restrict__ bias,
                                                   const float* __restrict__ resid,
                                                   float* __restrict__ out,
                                                   int M)
{
    const int K = 256, N = NN;
    __shared__ float sW[16 * 65];
    __shared__ float sX[16 * 64];

    const int tid = threadIdx.x;
    const int tx = tid & 15, ty = tid >> 4;
    const int n0 = blockIdx.x * 64, m0 = blockIdx.y * 64, b = blockIdx.z;
    const float* Xb = X + (size_t)b * K * N;

    float4 acc[4];
#pragma unroll
    for (int i = 0; i < 4; i++) acc[i] = make_float4(0.f, 0.f, 0.f, 0.f);

    for (int k0 = 0; k0 < K; k0 += 16) {
#pragma unroll
        for (int t = 0; t < 4; t++) {
            int idx = tid + t * 256;
            int o = idx >> 4, k = idx & 15;
            sW[k * 65 + o] = W[(size_t)(m0 + o) * K + k0 + k];
        }
#pragma unroll
        for (int t = 0; t < 4; t++) {
            int idx = tid + t * 256;
            int k = idx >> 6, n = idx & 63;
            sX[k * 64 + n] = Xb[(size_t)(k0 + k) * N + n0 + n];
        }
        __syncthreads();
#pragma unroll
        for (int kk = 0; kk < 16; kk++) {
            float4 xv = *reinterpret_cast<float4*>(sX + kk * 64 + tx * 4);
            float a0 = sW[kk * 65 + ty * 4 + 0];
            float a1 = sW[kk * 65 + ty * 4 + 1];
            float a2 = sW[kk * 65 + ty * 4 + 2];
            float a3 = sW[kk * 65 + ty * 4 + 3];
            acc[0].x += a0 * xv.x; acc[0].y += a0 * xv.y; acc[0].z += a0 * xv.z; acc[0].w += a0 * xv.w;
            acc[1].x += a1 * xv.x; acc[1].y += a1 * xv.y; acc[1].z += a1 * xv.z; acc[1].w += a1 * xv.w;
            acc[2].x += a2 * xv.x; acc[2].y += a2 * xv.y; acc[2].z += a2 * xv.z; acc[2].w += a2 * xv.w;
            acc[3].x += a3 * xv.x; acc[3].y += a3 * xv.y; acc[3].z += a3 * xv.z; acc[3].w += a3 * xv.w;
        }
        __syncthreads();
    }
#pragma unroll
    for (int i = 0; i < 4; i++) {
        const int o = m0 + ty * 4 + i;
        const float bv = bias[o];
        float4 r = acc[i];
        r.x += bv; r.y += bv; r.z += bv; r.w += bv;
        const size_t off = ((size_t)b * M + o) * N + n0 + tx * 4;
        if (resid) {
            float4 rv = *reinterpret_cast<const float4*>(resid + off);
            r.x += rv.x; r.y += rv.y; r.z += rv.z; r.w += rv.w;
        }
        *reinterpret_cast<float4*>(out + off) = r;
    }
}

// ================== flash attention (tf32 tensor-core mma) ==================
// Block: 64 queries x full c=256; streams 64-key K/V tiles (V reuses K buffer).
// S-phase: 8 warps as 4(q16) x 2(k32), m16n8k8 tf32 mma, K-dim = c = 256.
// O-phase: 8 warps as 2(q32) x 4(c64), accumulates O^T[q][c] in registers.
// SMEM (floats): sQ[256][72], sKV[256][72], sS[64][68], stats 3*64.
#define SQ_ST   72
#define SS_ST   68
#define ATT_SMEM_FLOATS (2 * 256 * SQ_ST + 64 * SS_ST + 192)
#define ATT_SMEM_BYTES  (ATT_SMEM_FLOATS * 4)

__global__ void __launch_bounds__(256) attn_kernel(const float* __restrict__ qkv,
                                                   float* __restrict__ outp)
{
    extern __shared__ float smf[];
    float* sQ  = smf;                       // [c][72]
    float* sKV = smf + 256 * SQ_ST;         // [c][72]
    float* sS  = smf + 2 * 256 * SQ_ST;     // [q][68]  (S, then P in-place)
    float* sMv = sS + 64 * SS_ST;
    float* sLv = sMv + 64;
    float* sAl = sLv + 64;

    const int tid  = threadIdx.x;
    const int lane = tid & 31;
    const int wid  = tid >> 5;
    const int gid  = lane >> 2;            // 0..7
    const int tig  = lane & 3;             // 0..3
    const int b    = blockIdx.y;
    const int q0   = blockIdx.x * 64;

    const float* Qg = qkv + (size_t)b * 3 * CC * NN;
    const float* Kg = Qg + (size_t)CC * NN;
    const float* Vg = Kg + (size_t)CC * NN;

    // load Q tile (scale 1/sqrt(256) folded in, rounded to tf32): sQ[c][q]
#pragma unroll
    for (int t = 0; t < 16; t++) {
        int idx = tid + t * 256;           // float4 units
        int c = idx >> 4, q4 = (idx & 15) << 2;
        float4 v = *reinterpret_cast<const float4*>(Qg + (size_t)c * NN + q0 + q4);
        v.x = tf32r(v.x * 0.0625f); v.y = tf32r(v.y * 0.0625f);
        v.z = tf32r(v.z * 0.0625f); v.w = tf32r(v.w * 0.0625f);
        *reinterpret_cast<float4*>(sQ + c * SQ_ST + q4) = v;
    }
    if (tid < 64) { sMv[tid] = -1e30f; sLv[tid] = 0.f; }

    const int qsS = (wid >> 1) * 16;       // S-phase query stripe
    const int ksS = (wid & 1) * 32;        // S-phase key half
    const int qsO = (wid >> 2) * 32;       // O-phase query half
    const int cg  = (wid & 3) * 64;        // O-phase channel group

    float4 oa[2][8];                       // O^T accum: 2 m-tiles x 8 n-tiles
#pragma unroll
    for (int m = 0; m < 2; m++)
#pragma unroll
        for (int n = 0; n < 8; n++) oa[m][n] = make_float4(0.f, 0.f, 0.f, 0.f);

    for (int kt = 0; kt < 64; kt++) {
        const int k0 = kt * 64;
        __syncthreads();                   // O-phase reads of prev V done
        // ---- load K tile: sKV[c][k] (tf32-rounded) ----
#pragma unroll
        for (int t = 0; t < 16; t++) {
            int idx = tid + t * 256;
            int c = idx >> 4, k4 = (idx & 15) << 2;
            float4 v = *reinterpret_cast<const float4*>(Kg + (size_t)c * NN + k0 + k4);
            v.x = tf32r(v.x); v.y = tf32r(v.y); v.z = tf32r(v.z); v.w = tf32r(v.w);
            *reinterpret_cast<float4*>(sKV + c * SQ_ST + k4) = v;
        }
        __syncthreads();

        // ---- S = Q^T K via mma (per warp: 16q x 32k, K-dim 256) ----
        float4 sd[4];
#pragma unroll
        for (int n = 0; n < 4; n++) sd[n] = make_float4(0.f, 0.f, 0.f, 0.f);
#pragma unroll 8
        for (int cs = 0; cs < 32; cs++) {
            const float* qp = sQ + (cs * 8 + tig) * SQ_ST + qsS + gid;
            uint32_t a0 = __float_as_uint(qp[0]);
            uint32_t a1 = __float_as_uint(qp[8]);
            uint32_t a2 = __float_as_uint(qp[4 * SQ_ST]);
            uint32_t a3 = __float_as_uint(qp[4 * SQ_ST + 8]);
            const float* kp = sKV + (cs * 8 + tig) * SQ_ST + ksS + gid;
#pragma unroll
            for (int nt = 0; nt < 4; nt++) {
                uint32_t b0 = __float_as_uint(kp[nt * 8]);
                uint32_t b1 = __float_as_uint(kp[4 * SQ_ST + nt * 8]);
                mma_tf32(sd[nt], a0, a1, a2, a3, b0, b1);
            }
        }
#pragma unroll
        for (int nt = 0; nt < 4; nt++) {
            int kc = ksS + nt * 8 + tig * 2;
            *reinterpret_cast<float2*>(sS + (qsS + gid) * SS_ST + kc) =
                make_float2(sd[nt].x, sd[nt].y);
            *reinterpret_cast<float2*>(sS + (qsS + gid + 8) * SS_ST + kc) =
                make_float2(sd[nt].z, sd[nt].w);
        }
        __syncthreads();                   // sS complete; K reads done

        // ---- load V tile (overwrites K buffer) ----
#pragma unroll
        for (int t = 0; t < 16; t++) {
            int idx = tid + t * 256;
            int c = idx >> 4, k4 = (idx & 15) << 2;
            float4 v = *reinterpret_cast<const float4*>(Vg + (size_t)c * NN + k0 + k4);
            v.x = tf32r(v.x); v.y = tf32r(v.y); v.z = tf32r(v.z); v.w = tf32r(v.w);
            *reinterpret_cast<float4*>(sKV + c * SQ_ST + k4) = v;
        }

        // ---- online softmax: 4 lanes per query row, 16 keys each ----
        {
            const int q = tid >> 2, kq = tid & 3;
            float* sp = sS + q * SS_ST + kq * 16;
            float4 r0 = *reinterpret_cast<float4*>(sp);
            float4 r1 = *reinterpret_cast<float4*>(sp + 4);
            float4 r2 = *reinterpret_cast<float4*>(sp + 8);
            float4 r3 = *reinterpret_cast<float4*>(sp + 12);
            float mx = fmaxf(fmaxf(fmaxf(r0.x, r0.y), fmaxf(r0.z, r0.w)),
                             fmaxf(fmaxf(r1.x, r1.y), fmaxf(r1.z, r1.w)));
            mx = fmaxf(mx, fmaxf(fmaxf(fmaxf(r2.x, r2.y), fmaxf(r2.z, r2.w)),
                                 fmaxf(fmaxf(r3.x, r3.y), fmaxf(r3.z, r3.w))));
            mx = fmaxf(mx, __shfl_xor_sync(0xffffffffu, mx, 1));
            mx = fmaxf(mx, __shfl_xor_sync(0xffffffffu, mx, 2));
            float mo = sMv[q];
            float mn = fmaxf(mo, mx);
            r0.x = __expf(r0.x - mn); r0.y = __expf(r0.y - mn);
            r0.z = __expf(r0.z - mn); r0.w = __expf(r0.w - mn);
            r1.x = __expf(r1.x - mn); r1.y = __expf(r1.y - mn);
            r1.z = __expf(r1.z - mn); r1.w = __expf(r1.w - mn);
            r2.x = __expf(r2.x - mn); r2.y = __expf(r2.y - mn);
            r2.z = __expf(r2.z - mn); r2.w = __expf(r2.w - mn);
            r3.x = __expf(r3.x - mn); r3.y = __expf(r3.y - mn);
            r3.z = __expf(r3.z - mn); r3.w = __expf(r3.w - mn);
            float ls = (r0.x + r0.y + r0.z + r0.w) + (r1.x + r1.y + r1.z + r1.w)
                     + (r2.x + r2.y + r2.z + r2.w) + (r3.x + r3.y + r3.z + r3.w);
            ls += __shfl_xor_sync(0xffffffffu, ls, 1);
            ls += __shfl_xor_sync(0xffffffffu, ls, 2);
            *reinterpret_cast<float4*>(sp)      = r0;
            *reinterpret_cast<float4*>(sp + 4)  = r1;
            *reinterpret_cast<float4*>(sp + 8)  = r2;
            *reinterpret_cast<float4*>(sp + 12) = r3;
            if (kq == 0) {
                float al = __expf(mo - mn);
                sAl[q] = al;
                sLv[q] = sLv[q] * al + ls;
                sMv[q] = mn;
            }
        }
        __syncthreads();                   // V + P + alpha ready

        // ---- O^T += P V^T via mma (per warp: 32q x 64c, K-dim 64) ----
        {
            float al00 = sAl[qsO + gid];
            float al01 = sAl[qsO + gid + 8];
            float al10 = sAl[qsO + 16 + gid];
            float al11 = sAl[qsO + 24 + gid];
#pragma unroll
            for (int nt = 0; nt < 8; nt++) {
                oa[0][nt].x *= al00; oa[0][nt].y *= al00;
                oa[0][nt].z *= al01; oa[0][nt].w *= al01;
                oa[1][nt].x *= al10; oa[1][nt].y *= al10;
                oa[1][nt].z *= al11; oa[1][nt].w *= al11;
            }
#pragma unroll 2
            for (int ks = 0; ks < 8; ks++) {
                const float* p0 = sS + (qsO + gid) * SS_ST + ks * 8 + tig;
                uint32_t A00 = __float_as_uint(p0[0]);
                uint32_t A01 = __float_as_uint(p0[8 * SS_ST]);
                uint32_t A02 = __float_as_uint(p0[4]);
                uint32_t A03 = __float_as_uint(p0[8 * SS_ST + 4]);
                const float* p1 = p0 + 16 * SS_ST;
                uint32_t A10 = __float_as_uint(p1[0]);
                uint32_t A11 = __float_as_uint(p1[8 * SS_ST]);
                uint32_t A12 = __float_as_uint(p1[4]);
                uint32_t A13 = __float_as_uint(p1[8 * SS_ST + 4]);
#pragma unroll
                for (int nt = 0; nt < 8; nt++) {
                    const float* vp = sKV + (cg + nt * 8 + gid) * SQ_ST + ks * 8 + tig;
                    uint32_t b0 = __float_as_uint(vp[0]);
                    uint32_t b1 = __float_as_uint(vp[4]);
                    mma_tf32(oa[0][nt], A00, A01, A02, A03, b0, b1);
                    mma_tf32(oa[1][nt], A10, A11, A12, A13, b0, b1);
                }
            }
        }
    }

    // ---- epilogue: divide by l, store O[c][q] ----
#pragma unroll
    for (int mt = 0; mt < 2; mt++) {
        const int qr0 = qsO + mt * 16 + gid;
        const float il0 = __frcp_rn(sLv[qr0]);
        const float il1 = __frcp_rn(sLv[qr0 + 8]);
#pragma unroll
        for (int nt = 0; nt < 8; nt++) {
            const int cc = cg + nt * 8 + tig * 2;
            float* op = outp + ((size_t)b * CC + cc) * NN + q0;
            op[qr0]          = oa[mt][nt].x * il0;
            op[NN + qr0]     = oa[mt][nt].y * il0;
            op[qr0 + 8]      = oa[mt][nt].z * il1;
            op[NN + qr0 + 8] = oa[mt][nt].w * il1;
        }
    }
}

// ================================ launch ====================================
extern "C" void kernel_launch(void* const* d_in, const int* in_sizes, int n_in,
                              void* d_out, int out_size)
{
    const float* x     = (const float*)d_in[0];
    const float* nw    = (const float*)d_in[1];
    const float* nb    = (const float*)d_in[2];
    const float* qkvw  = (const float*)d_in[3];
    const float* qkvb  = (const float*)d_in[4];
    const float* projw = (const float*)d_in[5];
    const float* projb = (const float*)d_in[6];
    float* out = (float*)d_out;

    float *hbuf, *qkvbuf, *abuf;
    cudaGetSymbolAddress((void**)&hbuf, g_h);
    cudaGetSymbolAddress((void**)&qkvbuf, g_qkv);
    cudaGetSymbolAddress((void**)&abuf, g_att);

    cudaFuncSetAttribute(attn_kernel, cudaFuncAttributeMaxDynamicSharedMemorySize,
                         ATT_SMEM_BYTES);

    gn_kernel<<<dim3(GG, BB), 256>>>(x, nw, nb, hbuf);
    gemm_kernel<<<dim3(NN / 64, (3 * CC) / 64, BB), 256>>>(qkvw, hbuf, qkvb, nullptr,
                                                           qkvbuf, 3 * CC);
    attn_kernel<<<dim3(NN / 64, BB), 256, ATT_SMEM_BYTES>>>(qkvbuf, abuf);
    gemm_kernel<<<dim3(NN / 64, CC / 64, BB), 256>>>(projw, abuf, projb, x, out, CC);
}

// round 5
// speedup vs baseline: 2.2697x; 1.0069x over previous
#include <cuda_runtime.h>
#include <cstddef>
#include <cstdint>

#define BB 8
#define CC 256
#define NN 4096            // tokens = 64*64
#define GG 32              // groups
#define CPG 8              // channels per group

// ---------------- scratch (device globals: allocation-free) ----------------
__device__ float g_h[(size_t)BB * CC * NN];          // normalized input
__device__ float g_qkv[(size_t)BB * 3 * CC * NN];    // q,k,v
__device__ float g_att[(size_t)BB * CC * NN];        // attention output

// ============================ helpers =======================================
__device__ __forceinline__ float tf32r(float x) {
    float r;
    asm("cvt.rna.tf32.f32 %0, %1;" : "=f"(r) : "f"(x));
    return r;
}

__device__ __forceinline__ void mma_tf32(float4& d,
                                         uint32_t a0, uint32_t a1, uint32_t a2, uint32_t a3,
                                         uint32_t b0, uint32_t b1) {
    asm volatile(
        "mma.sync.aligned.m16n8k8.row.col.f32.tf32.tf32.f32 "
        "{%0,%1,%2,%3}, {%4,%5,%6,%7}, {%8,%9}, {%0,%1,%2,%3};"
        : "+f"(d.x), "+f"(d.y), "+f"(d.z), "+f"(d.w)
        : "r"(a0), "r"(a1), "r"(a2), "r"(a3), "r"(b0), "r"(b1));
}

// ============================ GroupNorm =====================================
__global__ void __launch_bounds__(256) gn_kernel(const float* __restrict__ x,
                                                 const float* __restrict__ w,
                                                 const float* __restrict__ bg,
                                                 float* __restrict__ h)
{
    const int g = blockIdx.x, b = blockIdx.y;
    const size_t base = ((size_t)b * CC + (size_t)g * CPG) * NN;
    const float* xp = x + base;
    float* hp = h + base;
    const int tid = threadIdx.x;

    float s = 0.f, ss = 0.f;
#pragma unroll
    for (int t = 0; t < 32; t++) {
        float4 v = *reinterpret_cast<const float4*>(xp + (size_t)(t * 256 + tid) * 4);
        s  += v.x + v.y + v.z + v.w;
        ss += v.x * v.x + v.y * v.y + v.z * v.z + v.w * v.w;
    }
#pragma unroll
    for (int o = 16; o; o >>= 1) {
        s  += __shfl_xor_sync(0xffffffffu, s, o);
        ss += __shfl_xor_sync(0xffffffffu, ss, o);
    }
    __shared__ float rs[8], rss[8], stats[2];
    if ((tid & 31) == 0) { rs[tid >> 5] = s; rss[tid >> 5] = ss; }
    __syncthreads();
    if (tid == 0) {
        float ts = 0.f, tss = 0.f;
#pragma unroll
        for (int i = 0; i < 8; i++) { ts += rs[i]; tss += rss[i]; }
        const float inv_n = 1.0f / (CPG * NN);
        float mu = ts * inv_n;
        float var = tss * inv_n - mu * mu;
        stats[0] = mu;
        stats[1] = rsqrtf(var + 1e-5f);
    }
    __syncthreads();
    const float mu = stats[0], rsg = stats[1];
#pragma unroll
    for (int t = 0; t < 32; t++) {
        const int idx = (t * 256 + tid) * 4;
        const int c = g * CPG + (idx >> 12);
        const float sc = w[c] * rsg;
        const float sh = bg[c] - mu * sc;
        float4 v = *reinterpret_cast<const float4*>(xp + idx);
        v.x = v.x * sc + sh; v.y = v.y * sc + sh;
        v.z = v.z * sc + sh; v.w = v.w * sc + sh;
        *reinterpret_cast<float4*>(hp + idx) = v;
    }
}

// ============================ tiled SGEMM ===================================
__global__ void __launch_bounds__(256) gemm_kernel(const float* __restrict__ W,
                                                   const float* __restrict__ X,
                                                   const float* __restrict__ bias,
                                                   const float* __restrict__ resid,
                                                   float* __restrict__ out,
                                                   int M)
{
    const int K = 256, N = NN;
    __shared__ float sW[16 * 65];
    __shared__ float sX[16 * 64];

    const int tid = threadIdx.x;
    const int tx = tid & 15, ty = tid >> 4;
    const int n0 = blockIdx.x * 64, m0 = blockIdx.y * 64, b = blockIdx.z;
    const float* Xb = X + (size_t)b * K * N;

    float4 acc[4];
#pragma unroll
    for (int i = 0; i < 4; i++) acc[i] = make_float4(0.f, 0.f, 0.f, 0.f);

    for (int k0 = 0; k0 < K; k0 += 16) {
#pragma unroll
        for (int t = 0; t < 4; t++) {
            int idx = tid + t * 256;
            int o = idx >> 4, k = idx & 15;
            sW[k * 65 + o] = W[(size_t)(m0 + o) * K + k0 + k];
        }
#pragma unroll
        for (int t = 0; t < 4; t++) {
            int idx = tid + t * 256;
            int k = idx >> 6, n = idx & 63;
            sX[k * 64 + n] = Xb[(size_t)(k0 + k) * N + n0 + n];
        }
        __syncthreads();
#pragma unroll
        for (int kk = 0; kk < 16; kk++) {
            float4 xv = *reinterpret_cast<float4*>(sX + kk * 64 + tx * 4);
            float a0 = sW[kk * 65 + ty * 4 + 0];
            float a1 = sW[kk * 65 + ty * 4 + 1];
            float a2 = sW[kk * 65 + ty * 4 + 2];
            float a3 = sW[kk * 65 + ty * 4 + 3];
            acc[0].x += a0 * xv.x; acc[0].y += a0 * xv.y; acc[0].z += a0 * xv.z; acc[0].w += a0 * xv.w;
            acc[1].x += a1 * xv.x; acc[1].y += a1 * xv.y; acc[1].z += a1 * xv.z; acc[1].w += a1 * xv.w;
            acc[2].x += a2 * xv.x; acc[2].y += a2 * xv.y; acc[2].z += a2 * xv.z; acc[2].w += a2 * xv.w;
            acc[3].x += a3 * xv.x; acc[3].y += a3 * xv.y; acc[3].z += a3 * xv.z; acc[3].w += a3 * xv.w;
        }
        __syncthreads();
    }
#pragma unroll
    for (int i = 0; i < 4; i++) {
        const int o = m0 + ty * 4 + i;
        const float bv = bias[o];
        float4 r = acc[i];
        r.x += bv; r.y += bv; r.z += bv; r.w += bv;
        const size_t off = ((size_t)b * M + o) * N + n0 + tx * 4;
        if (resid) {
            float4 rv = *reinterpret_cast<const float4*>(resid + off);
            r.x += rv.x; r.y += rv.y; r.z += rv.z; r.w += rv.w;
        }
        *reinterpret_cast<float4*>(out + off) = r;
    }
}

// ================== flash attention (tf32 tensor-core mma) ==================
// Block: 64 queries x full c=256; streams 64-key K/V tiles (V reuses K buffer).
// S-phase: 8 warps as 4(q16) x 2(k32), m16n8k8 tf32 mma, K-dim = c = 256.
// O-phase: 8 warps as 2(q32) x 4(c64), accumulates O^T[q][c] in registers.
// SMEM (floats): sQ[256][72], sKV[256][72], sS[64][68], stats 3*64.
#define SQ_ST   72
#define SS_ST   68
#define ATT_SMEM_FLOATS (2 * 256 * SQ_ST + 64 * SS_ST + 192)
#define ATT_SMEM_BYTES  (ATT_SMEM_FLOATS * 4)

__global__ void __launch_bounds__(256) attn_kernel(const float* __restrict__ qkv,
                                                   float* __restrict__ outp)
{
    extern __shared__ float smf[];
    float* sQ  = smf;                       // [c][72]
    float* sKV = smf + 256 * SQ_ST;         // [c][72]
    float* sS  = smf + 2 * 256 * SQ_ST;     // [q][68]  (S, then P in-place)
    float* sMv = sS + 64 * SS_ST;
    float* sLv = sMv + 64;
    float* sAl = sLv + 64;

    const int tid  = threadIdx.x;
    const int lane = tid & 31;
    const int wid  = tid >> 5;
    const int gid  = lane >> 2;            // 0..7
    const int tig  = lane & 3;             // 0..3
    const int b    = blockIdx.y;
    const int q0   = blockIdx.x * 64;

    const float* Qg = qkv + (size_t)b * 3 * CC * NN;
    const float* Kg = Qg + (size_t)CC * NN;
    const float* Vg = Kg + (size_t)CC * NN;

    // load Q tile (scale 1/sqrt(256) folded in, rounded to tf32): sQ[c][q]
#pragma unroll
    for (int t = 0; t < 16; t++) {
        int idx = tid + t * 256;           // float4 units
        int c = idx >> 4, q4 = (idx & 15) << 2;
        float4 v = *reinterpret_cast<const float4*>(Qg + (size_t)c * NN + q0 + q4);
        v.x = tf32r(v.x * 0.0625f); v.y = tf32r(v.y * 0.0625f);
        v.z = tf32r(v.z * 0.0625f); v.w = tf32r(v.w * 0.0625f);
        *reinterpret_cast<float4*>(sQ + c * SQ_ST + q4) = v;
    }
    if (tid < 64) { sMv[tid] = -1e30f; sLv[tid] = 0.f; }

    const int qsS = (wid >> 1) * 16;       // S-phase query stripe
    const int ksS = (wid & 1) * 32;        // S-phase key half
    const int qsO = (wid >> 2) * 32;       // O-phase query half
    const int cg  = (wid & 3) * 64;        // O-phase channel group

    float4 oa[2][8];                       // O^T accum: 2 m-tiles x 8 n-tiles
#pragma unroll
    for (int m = 0; m < 2; m++)
#pragma unroll
        for (int n = 0; n < 8; n++) oa[m][n] = make_float4(0.f, 0.f, 0.f, 0.f);

    for (int kt = 0; kt < 64; kt++) {
        const int k0 = kt * 64;
        __syncthreads();                   // O-phase reads of prev V done
        // ---- load K tile: sKV[c][k] (tf32-rounded) ----
#pragma unroll
        for (int t = 0; t < 16; t++) {
            int idx = tid + t * 256;
            int c = idx >> 4, k4 = (idx & 15) << 2;
            float4 v = *reinterpret_cast<const float4*>(Kg + (size_t)c * NN + k0 + k4);
            v.x = tf32r(v.x); v.y = tf32r(v.y); v.z = tf32r(v.z); v.w = tf32r(v.w);
            *reinterpret_cast<float4*>(sKV + c * SQ_ST + k4) = v;
        }
        __syncthreads();

        // ---- S = Q^T K via mma (per warp: 16q x 32k, K-dim 256) ----
        float4 sd[4];
#pragma unroll
        for (int n = 0; n < 4; n++) sd[n] = make_float4(0.f, 0.f, 0.f, 0.f);
#pragma unroll 8
        for (int cs = 0; cs < 32; cs++) {
            const float* qp = sQ + (cs * 8 + tig) * SQ_ST + qsS + gid;
            uint32_t a0 = __float_as_uint(qp[0]);
            uint32_t a1 = __float_as_uint(qp[8]);
            uint32_t a2 = __float_as_uint(qp[4 * SQ_ST]);
            uint32_t a3 = __float_as_uint(qp[4 * SQ_ST + 8]);
            const float* kp = sKV + (cs * 8 + tig) * SQ_ST + ksS + gid;
#pragma unroll
            for (int nt = 0; nt < 4; nt++) {
                uint32_t b0 = __float_as_uint(kp[nt * 8]);
                uint32_t b1 = __float_as_uint(kp[4 * SQ_ST + nt * 8]);
                mma_tf32(sd[nt], a0, a1, a2, a3, b0, b1);
            }
        }
#pragma unroll
        for (int nt = 0; nt < 4; nt++) {
            int kc = ksS + nt * 8 + tig * 2;
            *reinterpret_cast<float2*>(sS + (qsS + gid) * SS_ST + kc) =
                make_float2(sd[nt].x, sd[nt].y);
            *reinterpret_cast<float2*>(sS + (qsS + gid + 8) * SS_ST + kc) =
                make_float2(sd[nt].z, sd[nt].w);
        }
        __syncthreads();                   // sS complete; K reads done

        // ---- load V tile (overwrites K buffer) ----
#pragma unroll
        for (int t = 0; t < 16; t++) {
            int idx = tid + t * 256;
            int c = idx >> 4, k4 = (idx & 15) << 2;
            float4 v = *reinterpret_cast<const float4*>(Vg + (size_t)c * NN + k0 + k4);
            v.x = tf32r(v.x); v.y = tf32r(v.y); v.z = tf32r(v.z); v.w = tf32r(v.w);
            *reinterpret_cast<float4*>(sKV + c * SQ_ST + k4) = v;
        }

        // ---- online softmax: 4 lanes per query row, 16 keys each ----
        {
            const int q = tid >> 2, kq = tid & 3;
            float* sp = sS + q * SS_ST + kq * 16;
            float4 r0 = *reinterpret_cast<float4*>(sp);
            float4 r1 = *reinterpret_cast<float4*>(sp + 4);
            float4 r2 = *reinterpret_cast<float4*>(sp + 8);
            float4 r3 = *reinterpret_cast<float4*>(sp + 12);
            float mx = fmaxf(fmaxf(fmaxf(r0.x, r0.y), fmaxf(r0.z, r0.w)),
                             fmaxf(fmaxf(r1.x, r1.y), fmaxf(r1.z, r1.w)));
            mx = fmaxf(mx, fmaxf(fmaxf(fmaxf(r2.x, r2.y), fmaxf(r2.z, r2.w)),
                                 fmaxf(fmaxf(r3.x, r3.y), fmaxf(r3.z, r3.w))));
            mx = fmaxf(mx, __shfl_xor_sync(0xffffffffu, mx, 1));
            mx = fmaxf(mx, __shfl_xor_sync(0xffffffffu, mx, 2));
            float mo = sMv[q];
            float mn = fmaxf(mo, mx);
            r0.x = __expf(r0.x - mn); r0.y = __expf(r0.y - mn);
            r0.z = __expf(r0.z - mn); r0.w = __expf(r0.w - mn);
            r1.x = __expf(r1.x - mn); r1.y = __expf(r1.y - mn);
            r1.z = __expf(r1.z - mn); r1.w = __expf(r1.w - mn);
            r2.x = __expf(r2.x - mn); r2.y = __expf(r2.y - mn);
            r2.z = __expf(r2.z - mn); r2.w = __expf(r2.w - mn);
            r3.x = __expf(r3.x - mn); r3.y = __expf(r3.y - mn);
            r3.z = __expf(r3.z - mn); r3.w = __expf(r3.w - mn);
            float ls = (r0.x + r0.y + r0.z + r0.w) + (r1.x + r1.y + r1.z + r1.w)
                     + (r2.x + r2.y + r2.z + r2.w) + (r3.x + r3.y + r3.z + r3.w);
            ls += __shfl_xor_sync(0xffffffffu, ls, 1);
            ls += __shfl_xor_sync(0xffffffffu, ls, 2);
            *reinterpret_cast<float4*>(sp)      = r0;
            *reinterpret_cast<float4*>(sp + 4)  = r1;
            *reinterpret_cast<float4*>(sp + 8)  = r2;
            *reinterpret_cast<float4*>(sp + 12) = r3;
            if (kq == 0) {
                float al = __expf(mo - mn);
                sAl[q] = al;
                sLv[q] = sLv[q] * al + ls;
                sMv[q] = mn;
            }
        }
        __syncthreads();                   // V + P + alpha ready

        // ---- O^T += P V^T via mma (per warp: 32q x 64c, K-dim 64) ----
        {
            float al00 = sAl[qsO + gid];
            float al01 = sAl[qsO + gid + 8];
            float al10 = sAl[qsO + 16 + gid];
            float al11 = sAl[qsO + 24 + gid];
#pragma unroll
            for (int nt = 0; nt < 8; nt++) {
                oa[0][nt].x *= al00; oa[0][nt].y *= al00;
                oa[0][nt].z *= al01; oa[0][nt].w *= al01;
                oa[1][nt].x *= al10; oa[1][nt].y *= al10;
                oa[1][nt].z *= al11; oa[1][nt].w *= al11;
            }
#pragma unroll 2
            for (int ks = 0; ks < 8; ks++) {
                const float* p0 = sS + (qsO + gid) * SS_ST + ks * 8 + tig;
                uint32_t A00 = __float_as_uint(p0[0]);
                uint32_t A01 = __float_as_uint(p0[8 * SS_ST]);
                uint32_t A02 = __float_as_uint(p0[4]);
                uint32_t A03 = __float_as_uint(p0[8 * SS_ST + 4]);
                const float* p1 = p0 + 16 * SS_ST;
                uint32_t A10 = __float_as_uint(p1[0]);
                uint32_t A11 = __float_as_uint(p1[8 * SS_ST]);
                uint32_t A12 = __float_as_uint(p1[4]);
                uint32_t A13 = __float_as_uint(p1[8 * SS_ST + 4]);
#pragma unroll
                for (int nt = 0; nt < 8; nt++) {
                    const float* vp = sKV + (cg + nt * 8 + gid) * SQ_ST + ks * 8 + tig;
                    uint32_t b0 = __float_as_uint(vp[0]);
                    uint32_t b1 = __float_as_uint(vp[4]);
                    mma_tf32(oa[0][nt], A00, A01, A02, A03, b0, b1);
                    mma_tf32(oa[1][nt], A10, A11, A12, A13, b0, b1);
                }
            }
        }
    }

    // ---- epilogue: divide by l, store O[c][q] ----
#pragma unroll
    for (int mt = 0; mt < 2; mt++) {
        const int qr0 = qsO + mt * 16 + gid;
        const float il0 = __frcp_rn(sLv[qr0]);
        const float il1 = __frcp_rn(sLv[qr0 + 8]);
#pragma unroll
        for (int nt = 0; nt < 8; nt++) {
            const int cc = cg + nt * 8 + tig * 2;
            float* op = outp + ((size_t)b * CC + cc) * NN + q0;
            op[qr0]          = oa[mt][nt].x * il0;
            op[NN + qr0]     = oa[mt][nt].y * il0;
            op[qr0 + 8]      = oa[mt][nt].z * il1;
            op[NN + qr0 + 8] = oa[mt][nt].w * il1;
        }
    }
}

// ================================ launch ====================================
extern "C" void kernel_launch(void* const* d_in, const int* in_sizes, int n_in,
                              void* d_out, int out_size)
{
    const float* x     = (const float*)d_in[0];
    const float* nw    = (const float*)d_in[1];
    const float* nb    = (const float*)d_in[2];
    const float* qkvw  = (const float*)d_in[3];
    const float* qkvb  = (const float*)d_in[4];
    const float* projw = (const float*)d_in[5];
    const float* projb = (const float*)d_in[6];
    float* out = (float*)d_out;

    float *hbuf, *qkvbuf, *abuf;
    cudaGetSymbolAddress((void**)&hbuf, g_h);
    cudaGetSymbolAddress((void**)&qkvbuf, g_qkv);
    cudaGetSymbolAddress((void**)&abuf, g_att);

    cudaFuncSetAttribute(attn_kernel, cudaFuncAttributeMaxDynamicSharedMemorySize,
                         ATT_SMEM_BYTES);

    gn_kernel<<<dim3(GG, BB), 256>>>(x, nw, nb, hbuf);
    gemm_kernel<<<dim3(NN / 64, (3 * CC) / 64, BB), 256>>>(qkvw, hbuf, qkvb, nullptr,
                                                           qkvbuf, 3 * CC);
    attn_kernel<<<dim3(NN / 64, BB), 256, ATT_SMEM_BYTES>>>(qkvbuf, abuf);
    gemm_kernel<<<dim3(NN / 64, CC / 64, BB), 256>>>(projw, abuf, projb, x, out, CC);
}

// round 6
// speedup vs baseline: 2.2907x; 1.0093x over previous
#include <cuda_runtime.h>
#include <cstddef>
#include <cstdint>

#define BB 8
#define CC 256
#define NN 4096            // tokens = 64*64
#define GG 32              // groups
#define CPG 8              // channels per group

// ---------------- scratch (device globals: allocation-free) ----------------
__device__ float g_h[(size_t)BB * CC * NN];          // normalized input
__device__ float g_qkv[(size_t)BB * 3 * CC * NN];    // q,k,v
__device__ float g_att[(size_t)BB * CC * NN];        // attention output

// ============================ helpers =======================================
__device__ __forceinline__ float tf32r(float x) {
    float r;
    asm("cvt.rna.tf32.f32 %0, %1;" : "=f"(r) : "f"(x));
    return r;
}

__device__ __forceinline__ void mma_tf32(float4& d,
                                         uint32_t a0, uint32_t a1, uint32_t a2, uint32_t a3,
                                         uint32_t b0, uint32_t b1) {
    asm volatile(
        "mma.sync.aligned.m16n8k8.row.col.f32.tf32.tf32.f32 "
        "{%0,%1,%2,%3}, {%4,%5,%6,%7}, {%8,%9}, {%0,%1,%2,%3};"
        : "+f"(d.x), "+f"(d.y), "+f"(d.z), "+f"(d.w)
        : "r"(a0), "r"(a1), "r"(a2), "r"(a3), "r"(b0), "r"(b1));
}

// ============================ GroupNorm =====================================
__global__ void __launch_bounds__(256) gn_kernel(const float* __restrict__ x,
                                                 const float* __restrict__ w,
                                                 const float* __restrict__ bg,
                                                 float* __restrict__ h)
{
    const int g = blockIdx.x, b = blockIdx.y;
    const size_t base = ((size_t)b * CC + (size_t)g * CPG) * NN;
    const float* xp = x + base;
    float* hp = h + base;
    const int tid = threadIdx.x;

    float s = 0.f, ss = 0.f;
#pragma unroll
    for (int t = 0; t < 32; t++) {
        float4 v = *reinterpret_cast<const float4*>(xp + (size_t)(t * 256 + tid) * 4);
        s  += v.x + v.y + v.z + v.w;
        ss += v.x * v.x + v.y * v.y + v.z * v.z + v.w * v.w;
    }
#pragma unroll
    for (int o = 16; o; o >>= 1) {
        s  += __shfl_xor_sync(0xffffffffu, s, o);
        ss += __shfl_xor_sync(0xffffffffu, ss, o);
    }
    __shared__ float rs[8], rss[8], stats[2];
    if ((tid & 31) == 0) { rs[tid >> 5] = s; rss[tid >> 5] = ss; }
    __syncthreads();
    if (tid == 0) {
        float ts = 0.f, tss = 0.f;
#pragma unroll
        for (int i = 0; i < 8; i++) { ts += rs[i]; tss += rss[i]; }
        const float inv_n = 1.0f / (CPG * NN);
        float mu = ts * inv_n;
        float var = tss * inv_n - mu * mu;
        stats[0] = mu;
        stats[1] = rsqrtf(var + 1e-5f);
    }
    __syncthreads();
    const float mu = stats[0], rsg = stats[1];
#pragma unroll
    for (int t = 0; t < 32; t++) {
        const int idx = (t * 256 + tid) * 4;
        const int c = g * CPG + (idx >> 12);
        const float sc = w[c] * rsg;
        const float sh = bg[c] - mu * sc;
        float4 v = *reinterpret_cast<const float4*>(xp + idx);
        v.x = v.x * sc + sh; v.y = v.y * sc + sh;
        v.z = v.z * sc + sh; v.w = v.w * sc + sh;
        *reinterpret_cast<float4*>(hp + idx) = v;
    }
}

// ============================ tiled SGEMM ===================================
__global__ void __launch_bounds__(256) gemm_kernel(const float* __restrict__ W,
                                                   const float* __restrict__ X,
                                                   const float* __restrict__ bias,
                                                   const float* __restrict__ resid,
                                                   float* __restrict__ out,
                                                   int M)
{
    const int K = 256, N = NN;
    __shared__ float sW[16 * 65];
    __shared__ float sX[16 * 64];

    const int tid = threadIdx.x;
    const int tx = tid & 15, ty = tid >> 4;
    const int n0 = blockIdx.x * 64, m0 = blockIdx.y * 64, b = blockIdx.z;
    const float* Xb = X + (size_t)b * K * N;

    float4 acc[4];
#pragma unroll
    for (int i = 0; i < 4; i++) acc[i] = make_float4(0.f, 0.f, 0.f, 0.f);

    for (int k0 = 0; k0 < K; k0 += 16) {
#pragma unroll
        for (int t = 0; t < 4; t++) {
            int idx = tid + t * 256;
            int o = idx >> 4, k = idx & 15;
            sW[k * 65 + o] = W[(size_t)(m0 + o) * K + k0 + k];
        }
#pragma unroll
        for (int t = 0; t < 4; t++) {
            int idx = tid + t * 256;
            int k = idx >> 6, n = idx & 63;
            sX[k * 64 + n] = Xb[(size_t)(k0 + k) * N + n0 + n];
        }
        __syncthreads();
#pragma unroll
        for (int kk = 0; kk < 16; kk++) {
            float4 xv = *reinterpret_cast<float4*>(sX + kk * 64 + tx * 4);
            float a0 = sW[kk * 65 + ty * 4 + 0];
            float a1 = sW[kk * 65 + ty * 4 + 1];
            float a2 = sW[kk * 65 + ty * 4 + 2];
            float a3 = sW[kk * 65 + ty * 4 + 3];
            acc[0].x += a0 * xv.x; acc[0].y += a0 * xv.y; acc[0].z += a0 * xv.z; acc[0].w += a0 * xv.w;
            acc[1].x += a1 * xv.x; acc[1].y += a1 * xv.y; acc[1].z += a1 * xv.z; acc[1].w += a1 * xv.w;
            acc[2].x += a2 * xv.x; acc[2].y += a2 * xv.y; acc[2].z += a2 * xv.z; acc[2].w += a2 * xv.w;
            acc[3].x += a3 * xv.x; acc[3].y += a3 * xv.y; acc[3].z += a3 * xv.z; acc[3].w += a3 * xv.w;
        }
        __syncthreads();
    }
#pragma unroll
    for (int i = 0; i < 4; i++) {
        const int o = m0 + ty * 4 + i;
        const float bv = bias[o];
        float4 r = acc[i];
        r.x += bv; r.y += bv; r.z += bv; r.w += bv;
        const size_t off = ((size_t)b * M + o) * N + n0 + tx * 4;
        if (resid) {
            float4 rv = *reinterpret_cast<const float4*>(resid + off);
            r.x += rv.x; r.y += rv.y; r.z += rv.z; r.w += rv.w;
        }
        *reinterpret_cast<float4*>(out + off) = r;
    }
}

// ================== flash attention (tf32 tensor-core mma) ==================
// Block: 64 queries x full c=256; streams 64-key K/V tiles (V reuses K buffer).
// S-phase: 8 warps as 4(q16) x 2(k32), m16n8k8 tf32 mma, K-dim = c = 256.
// O-phase: 8 warps as 2(q32) x 4(c64), accumulates O^T[q][c] in registers.
// SMEM (floats): sQ[256][72], sKV[256][72], sS[64][68], stats 3*64.
#define SQ_ST   72
#define SS_ST   68
#define ATT_SMEM_FLOATS (2 * 256 * SQ_ST + 64 * SS_ST + 192)
#define ATT_SMEM_BYTES  (ATT_SMEM_FLOATS * 4)

__global__ void __launch_bounds__(256) attn_kernel(const float* __restrict__ qkv,
                                                   float* __restrict__ outp)
{
    extern __shared__ float smf[];
    float* sQ  = smf;                       // [c][72]
    float* sKV = smf + 256 * SQ_ST;         // [c][72]
    float* sS  = smf + 2 * 256 * SQ_ST;     // [q][68]  (S, then P in-place)
    float* sMv = sS + 64 * SS_ST;
    float* sLv = sMv + 64;
    float* sAl = sLv + 64;

    const int tid  = threadIdx.x;
    const int lane = tid & 31;
    const int wid  = tid >> 5;
    const int gid  = lane >> 2;            // 0..7
    const int tig  = lane & 3;             // 0..3
    const int b    = blockIdx.y;
    const int q0   = blockIdx.x * 64;

    const float* Qg = qkv + (size_t)b * 3 * CC * NN;
    const float* Kg = Qg + (size_t)CC * NN;
    const float* Vg = Kg + (size_t)CC * NN;

    // load Q tile (scale 1/sqrt(256) folded in, rounded to tf32): sQ[c][q]
#pragma unroll
    for (int t = 0; t < 16; t++) {
        int idx = tid + t * 256;           // float4 units
        int c = idx >> 4, q4 = (idx & 15) << 2;
        float4 v = *reinterpret_cast<const float4*>(Qg + (size_t)c * NN + q0 + q4);
        v.x = tf32r(v.x * 0.0625f); v.y = tf32r(v.y * 0.0625f);
        v.z = tf32r(v.z * 0.0625f); v.w = tf32r(v.w * 0.0625f);
        *reinterpret_cast<float4*>(sQ + c * SQ_ST + q4) = v;
    }
    if (tid < 64) { sMv[tid] = -1e30f; sLv[tid] = 0.f; }

    const int qsS = (wid >> 1) * 16;       // S-phase query stripe
    const int ksS = (wid & 1) * 32;        // S-phase key half
    const int qsO = (wid >> 2) * 32;       // O-phase query half
    const int cg  = (wid & 3) * 64;        // O-phase channel group

    float4 oa[2][8];                       // O^T accum: 2 m-tiles x 8 n-tiles
#pragma unroll
    for (int m = 0; m < 2; m++)
#pragma unroll
        for (int n = 0; n < 8; n++) oa[m][n] = make_float4(0.f, 0.f, 0.f, 0.f);

    for (int kt = 0; kt < 64; kt++) {
        const int k0 = kt * 64;
        __syncthreads();                   // O-phase reads of prev V done
        // ---- load K tile: sKV[c][k] (tf32-rounded) ----
#pragma unroll
        for (int t = 0; t < 16; t++) {
            int idx = tid + t * 256;
            int c = idx >> 4, k4 = (idx & 15) << 2;
            float4 v = *reinterpret_cast<const float4*>(Kg + (size_t)c * NN + k0 + k4);
            v.x = tf32r(v.x); v.y = tf32r(v.y); v.z = tf32r(v.z); v.w = tf32r(v.w);
            *reinterpret_cast<float4*>(sKV + c * SQ_ST + k4) = v;
        }
        __syncthreads();

        // ---- S = Q^T K via mma (per warp: 16q x 32k, K-dim 256) ----
        float4 sd[4];
#pragma unroll
        for (int n = 0; n < 4; n++) sd[n] = make_float4(0.f, 0.f, 0.f, 0.f);
#pragma unroll 8
        for (int cs = 0; cs < 32; cs++) {
            const float* qp = sQ + (cs * 8 + tig) * SQ_ST + qsS + gid;
            uint32_t a0 = __float_as_uint(qp[0]);
            uint32_t a1 = __float_as_uint(qp[8]);
            uint32_t a2 = __float_as_uint(qp[4 * SQ_ST]);
            uint32_t a3 = __float_as_uint(qp[4 * SQ_ST + 8]);
            const float* kp = sKV + (cs * 8 + tig) * SQ_ST + ksS + gid;
#pragma unroll
            for (int nt = 0; nt < 4; nt++) {
                uint32_t b0 = __float_as_uint(kp[nt * 8]);
                uint32_t b1 = __float_as_uint(kp[4 * SQ_ST + nt * 8]);
                mma_tf32(sd[nt], a0, a1, a2, a3, b0, b1);
            }
        }
#pragma unroll
        for (int nt = 0; nt < 4; nt++) {
            int kc = ksS + nt * 8 + tig * 2;
            *reinterpret_cast<float2*>(sS + (qsS + gid) * SS_ST + kc) =
                make_float2(sd[nt].x, sd[nt].y);
            *reinterpret_cast<float2*>(sS + (qsS + gid + 8) * SS_ST + kc) =
                make_float2(sd[nt].z, sd[nt].w);
        }
        __syncthreads();                   // sS complete; K reads done

        // ---- load V tile (overwrites K buffer) ----
#pragma unroll
        for (int t = 0; t < 16; t++) {
            int idx = tid + t * 256;
            int c = idx >> 4, k4 = (idx & 15) << 2;
            float4 v = *reinterpret_cast<const float4*>(Vg + (size_t)c * NN + k0 + k4);
            v.x = tf32r(v.x); v.y = tf32r(v.y); v.z = tf32r(v.z); v.w = tf32r(v.w);
            *reinterpret_cast<float4*>(sKV + c * SQ_ST + k4) = v;
        }

        // ---- online softmax: 4 lanes per query row, 16 keys each ----
        {
            const int q = tid >> 2, kq = tid & 3;
            float* sp = sS + q * SS_ST + kq * 16;
            float4 r0 = *reinterpret_cast<float4*>(sp);
            float4 r1 = *reinterpret_cast<float4*>(sp + 4);
            float4 r2 = *reinterpret_cast<float4*>(sp + 8);
            float4 r3 = *reinterpret_cast<float4*>(sp + 12);
            float mx = fmaxf(fmaxf(fmaxf(r0.x, r0.y), fmaxf(r0.z, r0.w)),
                             fmaxf(fmaxf(r1.x, r1.y), fmaxf(r1.z, r1.w)));
            mx = fmaxf(mx, fmaxf(fmaxf(fmaxf(r2.x, r2.y), fmaxf(r2.z, r2.w)),
                                 fmaxf(fmaxf(r3.x, r3.y), fmaxf(r3.z, r3.w))));
            mx = fmaxf(mx, __shfl_xor_sync(0xffffffffu, mx, 1));
            mx = fmaxf(mx, __shfl_xor_sync(0xffffffffu, mx, 2));
            float mo = sMv[q];
            float mn = fmaxf(mo, mx);
            r0.x = __expf(r0.x - mn); r0.y = __expf(r0.y - mn);
            r0.z = __expf(r0.z - mn); r0.w = __expf(r0.w - mn);
            r1.x = __expf(r1.x - mn); r1.y = __expf(r1.y - mn);
            r1.z = __expf(r1.z - mn); r1.w = __expf(r1.w - mn);
            r2.x = __expf(r2.x - mn); r2.y = __expf(r2.y - mn);
            r2.z = __expf(r2.z - mn); r2.w = __expf(r2.w - mn);
            r3.x = __expf(r3.x - mn); r3.y = __expf(r3.y - mn);
            r3.z = __expf(r3.z - mn); r3.w = __expf(r3.w - mn);
            float ls = (r0.x + r0.y + r0.z + r0.w) + (r1.x + r1.y + r1.z + r1.w)
                     + (r2.x + r2.y + r2.z + r2.w) + (r3.x + r3.y + r3.z + r3.w);
            ls += __shfl_xor_sync(0xffffffffu, ls, 1);
            ls += __shfl_xor_sync(0xffffffffu, ls, 2);
            *reinterpret_cast<float4*>(sp)      = r0;
            *reinterpret_cast<float4*>(sp + 4)  = r1;
            *reinterpret_cast<float4*>(sp + 8)  = r2;
            *reinterpret_cast<float4*>(sp + 12) = r3;
            if (kq == 0) {
                float al = __expf(mo - mn);
                sAl[q] = al;
                sLv[q] = sLv[q] * al + ls;
                sMv[q] = mn;
            }
        }
        __syncthreads();                   // V + P + alpha ready

        // ---- O^T += P V^T via mma (per warp: 32q x 64c, K-dim 64) ----
        {
            float al00 = sAl[qsO + gid];
            float al01 = sAl[qsO + gid + 8];
            float al10 = sAl[qsO + 16 + gid];
            float al11 = sAl[qsO + 24 + gid];
#pragma unroll
            for (int nt = 0; nt < 8; nt++) {
                oa[0][nt].x *= al00; oa[0][nt].y *= al00;
                oa[0][nt].z *= al01; oa[0][nt].w *= al01;
                oa[1][nt].x *= al10; oa[1][nt].y *= al10;
                oa[1][nt].z *= al11; oa[1][nt].w *= al11;
            }
#pragma unroll 2
            for (int ks = 0; ks < 8; ks++) {
                const float* p0 = sS + (qsO + gid) * SS_ST + ks * 8 + tig;
                uint32_t A00 = __float_as_uint(p0[0]);
                uint32_t A01 = __float_as_uint(p0[8 * SS_ST]);
                uint32_t A02 = __float_as_uint(p0[4]);
                uint32_t A03 = __float_as_uint(p0[8 * SS_ST + 4]);
                const float* p1 = p0 + 16 * SS_ST;
                uint32_t A10 = __float_as_uint(p1[0]);
                uint32_t A11 = __float_as_uint(p1[8 * SS_ST]);
                uint32_t A12 = __float_as_uint(p1[4]);
                uint32_t A13 = __float_as_uint(p1[8 * SS_ST + 4]);
#pragma unroll
                for (int nt = 0; nt < 8; nt++) {
                    const float* vp = sKV + (cg + nt * 8 + gid) * SQ_ST + ks * 8 + tig;
                    uint32_t b0 = __float_as_uint(vp[0]);
                    uint32_t b1 = __float_as_uint(vp[4]);
                    mma_tf32(oa[0][nt], A00, A01, A02, A03, b0, b1);
                    mma_tf32(oa[1][nt], A10, A11, A12, A13, b0, b1);
                }
            }
        }
    }

    // ---- epilogue: divide by l, store O[c][q] ----
#pragma unroll
    for (int mt = 0; mt < 2; mt++) {
        const int qr0 = qsO + mt * 16 + gid;
        const float il0 = __frcp_rn(sLv[qr0]);
        const float il1 = __frcp_rn(sLv[qr0 + 8]);
#pragma unroll
        for (int nt = 0; nt < 8; nt++) {
            const int cc = cg + nt * 8 + tig * 2;
            float* op = outp + ((size_t)b * CC + cc) * NN + q0;
            op[qr0]          = oa[mt][nt].x * il0;
            op[NN + qr0]     = oa[mt][nt].y * il0;
            op[qr0 + 8]      = oa[mt][nt].z * il1;
            op[NN + qr0 + 8] = oa[mt][nt].w * il1;
        }
    }
}

// ================================ launch ====================================
extern "C" void kernel_launch(void* const* d_in, const int* in_sizes, int n_in,
                              void* d_out, int out_size)
{
    const float* x     = (const float*)d_in[0];
    const float* nw    = (const float*)d_in[1];
    const float* nb    = (const float*)d_in[2];
    const float* qkvw  = (const float*)d_in[3];
    const float* qkvb  = (const float*)d_in[4];
    const float* projw = (const float*)d_in[5];
    const float* projb = (const float*)d_in[6];
    float* out = (float*)d_out;

    float *hbuf, *qkvbuf, *abuf;
    cudaGetSymbolAddress((void**)&hbuf, g_h);
    cudaGetSymbolAddress((void**)&qkvbuf, g_qkv);
    cudaGetSymbolAddress((void**)&abuf, g_att);

    cudaFuncSetAttribute(attn_kernel, cudaFuncAttributeMaxDynamicSharedMemorySize,
                         ATT_SMEM_BYTES);

    gn_kernel<<<dim3(GG, BB), 256>>>(x, nw, nb, hbuf);
    gemm_kernel<<<dim3(NN / 64, (3 * CC) / 64, BB), 256>>>(qkvw, hbuf, qkvb, nullptr,
                                                           qkvbuf, 3 * CC);
    attn_kernel<<<dim3(NN / 64, BB), 256, ATT_SMEM_BYTES>>>(qkvbuf, abuf);
    gemm_kernel<<<dim3(NN / 64, CC / 64, BB), 256>>>(projw, abuf, projb, x, out, CC);
}

// round 11
// speedup vs baseline: 4.0085x; 1.7498x over previous
#include <cuda_runtime.h>
#include <cuda_bf16.h>
#include <cstddef>
#include <cstdint>

#define BB 8
#define CC 256
#define NN 4096            // tokens
#define GG 32
#define CPG 8

// ---------------- scratch (device globals: allocation-free) ----------------
__device__ float g_h[(size_t)BB * CC * NN];                     // normalized input
__device__ float g_qkv[(size_t)BB * 3 * CC * NN];               // fp32 q,k,v [b][o][n]
__device__ __nv_bfloat16 g_qb[(size_t)BB * NN * CC];            // Q  [b][q][c] (scaled)
__device__ __nv_bfloat16 g_kb[(size_t)BB * NN * CC];            // K  [b][k][c]
__device__ __nv_bfloat16 g_vb[(size_t)BB * CC * NN];            // V  [b][c][k]
__device__ float g_att[(size_t)BB * CC * NN];                   // attention out

// ============================ helpers =======================================
__device__ __forceinline__ uint32_t pack_bf16x2(float lo, float hi) {
    uint32_t r;
    asm("cvt.rn.bf16x2.f32 %0, %1, %2;" : "=r"(r) : "f"(hi), "f"(lo));
    return r;
}
__device__ __forceinline__ float ex2f(float x) {
    float r;
    asm("ex2.approx.ftz.f32 %0, %1;" : "=f"(r) : "f"(x));
    return r;
}
__device__ __forceinline__ void mma_bf16(float4& d,
                                         uint32_t a0, uint32_t a1, uint32_t a2, uint32_t a3,
                                         uint32_t b0, uint32_t b1) {
    asm volatile(
        "mma.sync.aligned.m16n8k16.row.col.f32.bf16.bf16.f32 "
        "{%0,%1,%2,%3}, {%4,%5,%6,%7}, {%8,%9}, {%0,%1,%2,%3};"
        : "+f"(d.x), "+f"(d.y), "+f"(d.z), "+f"(d.w)
        : "r"(a0), "r"(a1), "r"(a2), "r"(a3), "r"(b0), "r"(b1));
}

// ============================ GroupNorm =====================================
__global__ void __launch_bounds__(256) gn_kernel(const float* __restrict__ x,
                                                 const float* __restrict__ w,
                                                 const float* __restrict__ bg,
                                                 float* __restrict__ h)
{
    const int g = blockIdx.x, b = blockIdx.y;
    const size_t base = ((size_t)b * CC + (size_t)g * CPG) * NN;
    const float* xp = x + base;
    float* hp = h + base;
    const int tid = threadIdx.x;

    float s = 0.f, ss = 0.f;
#pragma unroll
    for (int t = 0; t < 32; t++) {
        float4 v = *reinterpret_cast<const float4*>(xp + (size_t)(t * 256 + tid) * 4);
        s  += v.x + v.y + v.z + v.w;
        ss += v.x * v.x + v.y * v.y + v.z * v.z + v.w * v.w;
    }
#pragma unroll
    for (int o = 16; o; o >>= 1) {
        s  += __shfl_xor_sync(0xffffffffu, s, o);
        ss += __shfl_xor_sync(0xffffffffu, ss, o);
    }
    __shared__ float rs[8], rss[8], stats[2];
    if ((tid & 31) == 0) { rs[tid >> 5] = s; rss[tid >> 5] = ss; }
    __syncthreads();
    if (tid == 0) {
        float ts = 0.f, tss = 0.f;
#pragma unroll
        for (int i = 0; i < 8; i++) { ts += rs[i]; tss += rss[i]; }
        const float inv_n = 1.0f / (CPG * NN);
        float mu = ts * inv_n;
        float var = tss * inv_n - mu * mu;
        stats[0] = mu;
        stats[1] = rsqrtf(var + 1e-5f);
    }
    __syncthreads();
    const float mu = stats[0], rsg = stats[1];
#pragma unroll
    for (int t = 0; t < 32; t++) {
        const int idx = (t * 256 + tid) * 4;
        const int c = g * CPG + (idx >> 12);
        const float sc = w[c] * rsg;
        const float sh = bg[c] - mu * sc;
        float4 v = *reinterpret_cast<const float4*>(xp + idx);
        v.x = v.x * sc + sh; v.y = v.y * sc + sh;
        v.z = v.z * sc + sh; v.w = v.w * sc + sh;
        *reinterpret_cast<float4*>(hp + idx) = v;
    }
}

// =================== tiled SGEMM (verified; qkv + proj) =====================
__global__ void __launch_bounds__(256) gemm_kernel(const float* __restrict__ W,
                                                   const float* __restrict__ X,
                                                   const float* __restrict__ bias,
                                                   const float* __restrict__ resid,
                                                   float* __restrict__ out,
                                                   int M)
{
    const int K = 256, N = NN;
    __shared__ float sW[16 * 65];
    __shared__ float sX[16 * 64];

    const int tid = threadIdx.x;
    const int tx = tid & 15, ty = tid >> 4;
    const int n0 = blockIdx.x * 64, m0 = blockIdx.y * 64, b = blockIdx.z;
    const float* Xb = X + (size_t)b * K * N;

    float4 acc[4];
#pragma unroll
    for (int i = 0; i < 4; i++) acc[i] = make_float4(0.f, 0.f, 0.f, 0.f);

    for (int k0 = 0; k0 < K; k0 += 16) {
#pragma unroll
        for (int t = 0; t < 4; t++) {
            int idx = tid + t * 256;
            int o = idx >> 4, k = idx & 15;
            sW[k * 65 + o] = W[(size_t)(m0 + o) * K + k0 + k];
        }
#pragma unroll
        for (int t = 0; t < 4; t++) {
            int idx = tid + t * 256;
            int k = idx >> 6, n = idx & 63;
            sX[k * 64 + n] = Xb[(size_t)(k0 + k) * N + n0 + n];
        }
        __syncthreads();
#pragma unroll
        for (int kk = 0; kk < 16; kk++) {
            float4 xv = *reinterpret_cast<float4*>(sX + kk * 64 + tx * 4);
            float a0 = sW[kk * 65 + ty * 4 + 0];
            float a1 = sW[kk * 65 + ty * 4 + 1];
            float a2 = sW[kk * 65 + ty * 4 + 2];
            float a3 = sW[kk * 65 + ty * 4 + 3];
            acc[0].x += a0 * xv.x; acc[0].y += a0 * xv.y; acc[0].z += a0 * xv.z; acc[0].w += a0 * xv.w;
            acc[1].x += a1 * xv.x; acc[1].y += a1 * xv.y; acc[1].z += a1 * xv.z; acc[1].w += a1 * xv.w;
            acc[2].x += a2 * xv.x; acc[2].y += a2 * xv.y; acc[2].z += a2 * xv.z; acc[2].w += a2 * xv.w;
            acc[3].x += a3 * xv.x; acc[3].y += a3 * xv.y; acc[3].z += a3 * xv.z; acc[3].w += a3 * xv.w;
        }
        __syncthreads();
    }
#pragma unroll
    for (int i = 0; i < 4; i++) {
        const int o = m0 + ty * 4 + i;
        const float bv = bias[o];
        float4 r = acc[i];
        r.x += bv; r.y += bv; r.z += bv; r.w += bv;
        const size_t off = ((size_t)b * M + o) * N + n0 + tx * 4;
        if (resid) {
            float4 rv = *reinterpret_cast<const float4*>(resid + off);
            r.x += rv.x; r.y += rv.y; r.z += rv.z; r.w += rv.w;
        }
        *reinterpret_cast<float4*>(out + off) = r;
    }
}

// ============ fp32 qkv -> bf16 operand buffers (transpose q/k) ==============
__global__ void __launch_bounds__(256) conv_kernel(const float* __restrict__ qkv,
                                                   __nv_bfloat16* __restrict__ qb,
                                                   __nv_bfloat16* __restrict__ kb,
                                                   __nv_bfloat16* __restrict__ vb)
{
    __shared__ float tile[32][33];
    const int b = blockIdx.z / 3, which = blockIdx.z % 3;
    const int n0 = blockIdx.x * 32, c0 = blockIdx.y * 32;
    const int tx = threadIdx.x & 31, ty = threadIdx.x >> 5;   // 32 x 8

    const float* src = qkv + ((size_t)b * 3 * CC + which * CC) * NN;
#pragma unroll
    for (int i = 0; i < 4; i++) {
        int c = c0 + ty + i * 8;
        tile[ty + i * 8][tx] = src[(size_t)c * NN + n0 + tx];
    }
    __syncthreads();

    if (which == 2) {
#pragma unroll
        for (int i = 0; i < 4; i++) {
            int c = c0 + ty + i * 8;
            vb[((size_t)b * CC + c) * NN + n0 + tx] =
                __float2bfloat16(tile[ty + i * 8][tx]);
        }
    } else {
        const float scl = (which == 0) ? 0.09016844f : 1.0f;  // log2(e)/16
        __nv_bfloat16* dst = (which == 0) ? qb : kb;
#pragma unroll
        for (int i = 0; i < 4; i++) {
            int n = n0 + ty + i * 8;
            dst[((size_t)b * NN + n) * CC + c0 + tx] =
                __float2bfloat16(tile[tx][ty + i * 8] * scl);
        }
    }
}

// ======= flash attention: bf16 m16n8k16, explicit per-lane fragment LDS =====
// CTA: 128 q, 8 warps (warp = 16 q x 64 keys x 256 channels), 64-key tiles.
// Per-thread l holds a 16-of-64-keys partial; reduced across the 4 row-lanes
// ONCE at the end (alpha is row-uniform each iter, so l is linear in partials).
#define QST 264                          // bf16 elems/row (528B)
#define VST 72                           // 144B
#define SQ_OFF 0
#define SK_OFF (128 * 528)               // 67584
#define SV_OFF (SK_OFF + 64 * 528)       // 101376
#define ATT_SMEM (SV_OFF + 256 * 144)    // 138240

__global__ void __launch_bounds__(256, 1) attn4_kernel(const __nv_bfloat16* __restrict__ qb,
                                                       const __nv_bfloat16* __restrict__ kb,
                                                       const __nv_bfloat16* __restrict__ vb,
                                                       float* __restrict__ outp)
{
    extern __shared__ char sm[];
    __nv_bfloat16* sQ = reinterpret_cast<__nv_bfloat16*>(sm + SQ_OFF);
    __nv_bfloat16* sK = reinterpret_cast<__nv_bfloat16*>(sm + SK_OFF);
    __nv_bfloat16* sV = reinterpret_cast<__nv_bfloat16*>(sm + SV_OFF);

    const int tid  = threadIdx.x;
    const int lane = tid & 31;
    const int wid  = tid >> 5;
    const int g    = lane >> 2;
    const int t    = lane & 3;
    const int b    = blockIdx.y;
    const int q0   = blockIdx.x * 128;

    const __nv_bfloat16* Qg = qb + ((size_t)b * NN + q0) * 256;
    const __nv_bfloat16* Kg = kb + (size_t)b * NN * 256;
    const __nv_bfloat16* Vg = vb + (size_t)b * CC * NN;

    // ---- load Q tile: [128][256] bf16, row stride 528B ----
#pragma unroll
    for (int tt = 0; tt < 16; tt++) {
        int idx = tid + tt * 256;          // 16B chunks
        int r = idx >> 5, ch = idx & 31;
        *reinterpret_cast<uint4*>(sm + SQ_OFF + r * 528 + ch * 16) =
            *reinterpret_cast<const uint4*>(Qg + (size_t)r * 256 + ch * 8);
    }

    float4 oacc[32];
#pragma unroll
    for (int j = 0; j < 32; j++) oacc[j] = make_float4(0.f, 0.f, 0.f, 0.f);
    float m0r = -1e30f, m1r = -1e30f, l0r = 0.f, l1r = 0.f;

    const int rq = wid * 16 + g;

    for (int kt = 0; kt < 64; kt++) {
        const int k0 = kt * 64;
        __syncthreads();                   // prev-iter tile reads complete
        // ---- load K tile [64][256] and V tile [256][64] ----
#pragma unroll
        for (int tt = 0; tt < 8; tt++) {
            int idx = tid + tt * 256;
            int r = idx >> 5, ch = idx & 31;
            *reinterpret_cast<uint4*>(sm + SK_OFF + r * 528 + ch * 16) =
                *reinterpret_cast<const uint4*>(Kg + (size_t)(k0 + r) * 256 + ch * 8);
        }
#pragma unroll
        for (int tt = 0; tt < 8; tt++) {
            int idx = tid + tt * 256;
            int c = idx >> 3, ch = idx & 7;
            *reinterpret_cast<uint4*>(sm + SV_OFF + c * 144 + ch * 16) =
                *reinterpret_cast<const uint4*>(Vg + (size_t)c * NN + k0 + ch * 8);
        }
        __syncthreads();

        // ---- S = Q K^T : warp 16q x 64k, K-dim 256 ----
        float4 d[8];
#pragma unroll
        for (int j = 0; j < 8; j++) d[j] = make_float4(0.f, 0.f, 0.f, 0.f);
#pragma unroll 4
        for (int kc = 0; kc < 16; kc++) {
            const int col = kc * 16 + 2 * t;
            uint32_t a0 = *reinterpret_cast<const uint32_t*>(sQ + rq * QST + col);
            uint32_t a1 = *reinterpret_cast<const uint32_t*>(sQ + (rq + 8) * QST + col);
            uint32_t a2 = *reinterpret_cast<const uint32_t*>(sQ + rq * QST + col + 8);
            uint32_t a3 = *reinterpret_cast<const uint32_t*>(sQ + (rq + 8) * QST + col + 8);
#pragma unroll
            for (int ng = 0; ng < 4; ng++) {
                uint32_t b0 = *reinterpret_cast<const uint32_t*>(sK + (ng * 16 + g) * QST + col);
                uint32_t b1 = *reinterpret_cast<const uint32_t*>(sK + (ng * 16 + g) * QST + col + 8);
                mma_bf16(d[2 * ng], a0, a1, a2, a3, b0, b1);
                uint32_t c0 = *reinterpret_cast<const uint32_t*>(sK + (ng * 16 + 8 + g) * QST + col);
                uint32_t c1 = *reinterpret_cast<const uint32_t*>(sK + (ng * 16 + 8 + g) * QST + col + 8);
                mma_bf16(d[2 * ng + 1], a0, a1, a2, a3, c0, c1);
            }
        }

        // ---- online softmax (S in log2 units; Q pre-scaled by log2e/16) ----
        float nm0 = -1e30f, nm1 = -1e30f;
#pragma unroll
        for (int j = 0; j < 8; j++) {
            nm0 = fmaxf(nm0, fmaxf(d[j].x, d[j].y));
            nm1 = fmaxf(nm1, fmaxf(d[j].z, d[j].w));
        }
        nm0 = fmaxf(nm0, __shfl_xor_sync(0xffffffffu, nm0, 1));
        nm0 = fmaxf(nm0, __shfl_xor_sync(0xffffffffu, nm0, 2));
        nm1 = fmaxf(nm1, __shfl_xor_sync(0xffffffffu, nm1, 1));
        nm1 = fmaxf(nm1, __shfl_xor_sync(0xffffffffu, nm1, 2));
        nm0 = fmaxf(m0r, nm0);
        nm1 = fmaxf(m1r, nm1);
        const float al0 = ex2f(m0r - nm0);
        const float al1 = ex2f(m1r - nm1);
        m0r = nm0; m1r = nm1;

        uint32_t pa[4][4];
        float ls0 = 0.f, ls1 = 0.f;
#pragma unroll
        for (int kc = 0; kc < 4; kc++) {
            float p00 = ex2f(d[2 * kc].x - nm0), p01 = ex2f(d[2 * kc].y - nm0);
            float p02 = ex2f(d[2 * kc].z - nm1), p03 = ex2f(d[2 * kc].w - nm1);
            float p10 = ex2f(d[2 * kc + 1].x - nm0), p11 = ex2f(d[2 * kc + 1].y - nm0);
            float p12 = ex2f(d[2 * kc + 1].z - nm1), p13 = ex2f(d[2 * kc + 1].w - nm1);
            ls0 += (p00 + p01) + (p10 + p11);
            ls1 += (p02 + p03) + (p12 + p13);
            pa[kc][0] = pack_bf16x2(p00, p01);   // A a0: (row g,  k 2t..2t+1)
            pa[kc][1] = pack_bf16x2(p02, p03);   // A a1: (row g+8, k 2t..)
            pa[kc][2] = pack_bf16x2(p10, p11);   // A a2: (row g,  k 2t+8..)
            pa[kc][3] = pack_bf16x2(p12, p13);   // A a3: (row g+8, k 2t+8..)
        }
        l0r = l0r * al0 + ls0;                   // per-thread 16-key partial
        l1r = l1r * al1 + ls1;

        // rescale O only when max moved (warp-uniform check)
        if (!__all_sync(0xffffffffu, (al0 == 1.f) & (al1 == 1.f))) {
#pragma unroll
            for (int j = 0; j < 32; j++) {
                oacc[j].x *= al0; oacc[j].y *= al0;
                oacc[j].z *= al1; oacc[j].w *= al1;
            }
        }

        // ---- O += P V^T : warp 16q x 256c, K-dim 64 ----
#pragma unroll 4
        for (int cg = 0; cg < 16; cg++) {
#pragma unroll
            for (int kc = 0; kc < 4; kc++) {
                const int col = kc * 16 + 2 * t;
                uint32_t b0 = *reinterpret_cast<const uint32_t*>(sV + (cg * 16 + g) * VST + col);
                uint32_t b1 = *reinterpret_cast<const uint32_t*>(sV + (cg * 16 + g) * VST + col + 8);
                mma_bf16(oacc[2 * cg], pa[kc][0], pa[kc][1], pa[kc][2], pa[kc][3], b0, b1);
                uint32_t c0 = *reinterpret_cast<const uint32_t*>(sV + (cg * 16 + 8 + g) * VST + col);
                uint32_t c1 = *reinterpret_cast<const uint32_t*>(sV + (cg * 16 + 8 + g) * VST + col + 8);
                mma_bf16(oacc[2 * cg + 1], pa[kc][0], pa[kc][1], pa[kc][2], pa[kc][3], c0, c1);
            }
        }
    }

    // ---- THE FIX: combine the 4 per-lane l partials of each row ----
    l0r += __shfl_xor_sync(0xffffffffu, l0r, 1);
    l0r += __shfl_xor_sync(0xffffffffu, l0r, 2);
    l1r += __shfl_xor_sync(0xffffffffu, l1r, 1);
    l1r += __shfl_xor_sync(0xffffffffu, l1r, 2);

    // ---- epilogue: O / l -> out[c][q] ----
    const float inv0 = __frcp_rn(l0r);
    const float inv1 = __frcp_rn(l1r);
    const int qr0 = q0 + wid * 16 + g;
    const int qr1 = qr0 + 8;
    const int cbase = t * 2;
#pragma unroll
    for (int j = 0; j < 32; j++) {
        const int c = 8 * j + cbase;
        float* bp = outp + ((size_t)b * CC + c) * NN;
        bp[qr0]      = oacc[j].x * inv0;
        bp[NN + qr0] = oacc[j].y * inv0;
        bp[qr1]      = oacc[j].z * inv1;
        bp[NN + qr1] = oacc[j].w * inv1;
    }
}

// ================================ launch ====================================
extern "C" void kernel_launch(void* const* d_in, const int* in_sizes, int n_in,
                              void* d_out, int out_size)
{
    const float* x     = (const float*)d_in[0];
    const float* nw    = (const float*)d_in[1];
    const float* nb    = (const float*)d_in[2];
    const float* qkvw  = (const float*)d_in[3];
    const float* qkvb  = (const float*)d_in[4];
    const float* projw = (const float*)d_in[5];
    const float* projb = (const float*)d_in[6];
    float* out = (float*)d_out;

    float *hbuf, *qkvbuf, *abuf;
    __nv_bfloat16 *qbp, *kbp, *vbp;
    cudaGetSymbolAddress((void**)&hbuf, g_h);
    cudaGetSymbolAddress((void**)&qkvbuf, g_qkv);
    cudaGetSymbolAddress((void**)&abuf, g_att);
    cudaGetSymbolAddress((void**)&qbp, g_qb);
    cudaGetSymbolAddress((void**)&kbp, g_kb);
    cudaGetSymbolAddress((void**)&vbp, g_vb);

    cudaFuncSetAttribute(attn4_kernel, cudaFuncAttributeMaxDynamicSharedMemorySize,
                         ATT_SMEM);

    gn_kernel<<<dim3(GG, BB), 256>>>(x, nw, nb, hbuf);
    gemm_kernel<<<dim3(NN / 64, 12, BB), 256>>>(qkvw, hbuf, qkvb, nullptr,
                                                qkvbuf, 3 * CC);
    conv_kernel<<<dim3(NN / 32, CC / 32, BB * 3), 256>>>(qkvbuf, qbp, kbp, vbp);
    attn4_kernel<<<dim3(NN / 128, BB), 256, ATT_SMEM>>>(qbp, kbp, vbp, abuf);
    gemm_kernel<<<dim3(NN / 64, CC / 64, BB), 256>>>(projw, abuf, projb, x, out, CC);
}